// round 7
// baseline (speedup 1.0000x reference)
#include <cuda_runtime.h>
#include <cuda_bf16.h>
#include <math.h>
#include <stdint.h>

// Problem constants
#define LL 4
#define BB 2
#define SS 4096
#define HH 2048
#define NN 256
#define BSQ 16
#define NHH 16
#define DHH 128
// GEMM dims: M = B*N*L = 2048, K = H = 2048, N_out = NH*DH = 2048
#define GM 2048
#define GK 2048
#define GN 2048
#define BM 128
#define BN 128
#define BKK 32

#define ATT_SCALE 0.08838834764831843f  // 1/sqrt(128)

// Scratch for projected context K/V: (B*N*L) x (NH*DH) f32, 16 MB each
__device__ float g_kchs[(size_t)GM * GN];
__device__ float g_vchs[(size_t)GM * GN];
// Decoded context indices + mask
__device__ int g_ctx[BB * NN];
__device__ float g_maskf[BB * NN];

__device__ __forceinline__ uint32_t f2tf32(float x) {
    uint32_t y;
    asm("cvt.rna.tf32.f32 %0, %1;" : "=r"(y) : "f"(x));
    return y;
}

__device__ __forceinline__ void mma_tf32(float c[4], uint32_t a0, uint32_t a1,
                                         uint32_t a2, uint32_t a3,
                                         uint32_t b0, uint32_t b1) {
    asm volatile(
        "mma.sync.aligned.m16n8k8.row.col.f32.tf32.tf32.f32 "
        "{%0,%1,%2,%3}, {%4,%5,%6,%7}, {%8,%9}, {%0,%1,%2,%3};\n"
        : "+f"(c[0]), "+f"(c[1]), "+f"(c[2]), "+f"(c[3])
        : "r"(a0), "r"(a1), "r"(a2), "r"(a3), "r"(b0), "r"(b1));
}

// ---------------------------------------------------------------------------
// Decode anchors (d_in[1]) and mask (d_in[2]) with width detection.
// Anchors: int32 vs int64 sniff — for int32 data, the high 32-bit word of the
//   first 64 8-byte reads contains odd-index sorted anchors (not all zero);
//   for genuine int64 anchors (< 4096) all high words are zero.
// Mask: bool materialized as int32 vs int8 — read as int32: if EVERY one of
//   the 512 int32 values (2048 bytes; safe: int8 hypothesis also owns >= 512
//   bytes only if int32... we only read 512 bytes under int8 view) is 0 or 1,
//   the buffer is int32-width (int8 all-ones would read as 0x01010101).
//   To stay in bounds under the int8 hypothesis we sniff width using only the
//   first 128 int32 words (512 bytes), which suffices: any nonzero int8-bool
//   content produces a packed value > 1 there.
// ---------------------------------------------------------------------------
__global__ void decode_small_kernel(const unsigned char* __restrict__ anc_b,
                                    const unsigned char* __restrict__ msk_b) {
    __shared__ int is32flag, maskPacked;
    if (threadIdx.x == 0) { is32flag = 0; maskPacked = 0; }
    __syncthreads();

    const long long* a64 = (const long long*)anc_b;
    const int* a32 = (const int*)anc_b;
    for (int i = threadIdx.x; i < 64; i += blockDim.x) {   // first 512 bytes
        if ((a64[i] >> 32) != 0) atomicOr(&is32flag, 1);
    }
    const unsigned int* m32 = (const unsigned int*)msk_b;
    for (int i = threadIdx.x; i < 128; i += blockDim.x) {  // first 512 bytes
        if (m32[i] > 1u) atomicOr(&maskPacked, 1);         // packed int8 bools
    }
    __syncthreads();
    const int is32 = is32flag;
    const int mpack = maskPacked;
    for (int i = threadIdx.x; i < BB * NN; i += blockDim.x) {
        int a = is32 ? a32[i] : (int)a64[i];
        int ctx = a - 1;
        if (ctx < 0) ctx = 0;
        g_ctx[i] = ctx;
        unsigned int mv = mpack ? (unsigned int)msk_b[i] : m32[i];
        g_maskf[i] = mv ? 1.f : 0.f;
    }
}

// ---------------------------------------------------------------------------
// GEMM with fused gather:  out[m, n] = sum_k hs_row(m)[k] * W[k, n]
//   m = (b*N + n_blk)*L + l ; hs_row base = ((l*B + b)*S + ctx[b,n_blk]) * H
// gridDim = (GN/BN, GM/BM, 2) ; z=0 -> W_kc -> g_kchs, z=1 -> W_vc -> g_vchs
// ---------------------------------------------------------------------------
__global__ __launch_bounds__(256)
void gemm_gather_kernel(const float* __restrict__ hs,
                        const float* __restrict__ Wk,
                        const float* __restrict__ Wv) {
    __shared__ uint32_t As[BM][BKK + 1];   // 128 x 33
    __shared__ uint32_t Bs[BKK][BN + 4];   // 32 x 132
    __shared__ int rowoff[BM];

    const int t = threadIdx.x;
    const int m0 = blockIdx.y * BM;
    const int n0 = blockIdx.x * BN;
    const float* __restrict__ W = (blockIdx.z == 0) ? Wk : Wv;
    float* __restrict__ dst = (blockIdx.z == 0) ? g_kchs : g_vchs;

    if (t < BM) {
        int m = m0 + t;
        int b = m >> 10;           // / (N*L)=1024
        int rem = m & 1023;
        int nb = rem >> 2;         // / L
        int l = rem & 3;
        int ctx = g_ctx[b * NN + nb];
        rowoff[t] = ((l * BB + b) * SS + ctx) * HH;
    }
    __syncthreads();

    const int lane = t & 31;
    const int wid = t >> 5;
    const int wm = wid >> 1;   // 0..3
    const int wn = wid & 1;    // 0..1
    const int qr = lane >> 2;  // 0..7
    const int qc = lane & 3;   // 0..3

    float acc[2][8][4];
#pragma unroll
    for (int mt = 0; mt < 2; mt++)
#pragma unroll
        for (int nt = 0; nt < 8; nt++)
#pragma unroll
            for (int i = 0; i < 4; i++) acc[mt][nt][i] = 0.f;

    for (int k0 = 0; k0 < GK; k0 += BKK) {
        // Load A tile (gathered rows), 4 float4 per thread
#pragma unroll
        for (int p = 0; p < 4; p++) {
            int row = (t >> 3) + p * 32;
            int cg = (t & 7) * 4;
            const float4 f = *(const float4*)(hs + (size_t)rowoff[row] + k0 + cg);
            As[row][cg + 0] = f2tf32(f.x);
            As[row][cg + 1] = f2tf32(f.y);
            As[row][cg + 2] = f2tf32(f.z);
            As[row][cg + 3] = f2tf32(f.w);
        }
        // Load B tile (W rows k0..k0+31, cols n0..n0+127)
#pragma unroll
        for (int p = 0; p < 4; p++) {
            int row = (t >> 5) + p * 8;
            int cg = (t & 31) * 4;
            const float4 f = *(const float4*)(W + (size_t)(k0 + row) * GN + n0 + cg);
            Bs[row][cg + 0] = f2tf32(f.x);
            Bs[row][cg + 1] = f2tf32(f.y);
            Bs[row][cg + 2] = f2tf32(f.z);
            Bs[row][cg + 3] = f2tf32(f.w);
        }
        __syncthreads();

#pragma unroll
        for (int ks = 0; ks < 4; ks++) {
            uint32_t afr[2][4];
            uint32_t bfr[8][2];
#pragma unroll
            for (int mt = 0; mt < 2; mt++) {
                int rb = wm * 32 + mt * 16;
                afr[mt][0] = As[rb + qr][ks * 8 + qc];
                afr[mt][1] = As[rb + qr + 8][ks * 8 + qc];
                afr[mt][2] = As[rb + qr][ks * 8 + qc + 4];
                afr[mt][3] = As[rb + qr + 8][ks * 8 + qc + 4];
            }
#pragma unroll
            for (int nt = 0; nt < 8; nt++) {
                int col = wn * 64 + nt * 8 + qr;
                bfr[nt][0] = Bs[ks * 8 + qc][col];
                bfr[nt][1] = Bs[ks * 8 + qc + 4][col];
            }
#pragma unroll
            for (int mt = 0; mt < 2; mt++)
#pragma unroll
                for (int nt = 0; nt < 8; nt++)
                    mma_tf32(acc[mt][nt], afr[mt][0], afr[mt][1], afr[mt][2],
                             afr[mt][3], bfr[nt][0], bfr[nt][1]);
        }
        __syncthreads();
    }

    // Epilogue
#pragma unroll
    for (int mt = 0; mt < 2; mt++) {
#pragma unroll
        for (int nt = 0; nt < 8; nt++) {
            int r0 = m0 + wm * 32 + mt * 16 + qr;
            int c0 = n0 + wn * 64 + nt * 8 + 2 * qc;
            *(float2*)(dst + (size_t)r0 * GN + c0) =
                make_float2(acc[mt][nt][0], acc[mt][nt][1]);
            *(float2*)(dst + (size_t)(r0 + 8) * GN + c0) =
                make_float2(acc[mt][nt][2], acc[mt][nt][3]);
        }
    }
}

// ---------------------------------------------------------------------------
// Attention: one block per (h, n, b). 16 queries x 20 keys x 128 dims.
// keys/values = [4 projected context rows] ++ [16 block rows].
// ---------------------------------------------------------------------------
#define SKP 132

__global__ __launch_bounds__(256)
void attn_kernel(const float* __restrict__ q, const float* __restrict__ k,
                 const float* __restrict__ v,
                 float* __restrict__ out) {
    __shared__ float sq[16][SKP];
    __shared__ float sk[20][SKP];
    __shared__ float sv[20][SKP];
    __shared__ float sattn[16][20];

    const int t = threadIdx.x;
    const int h = blockIdx.x;
    const int n = blockIdx.y;
    const int b = blockIdx.z;

    const size_t qkv_base = (((size_t)(b * (NN * BSQ) + n * BSQ)) * NHH + h) * DHH;
    const size_t chs_base = ((size_t)((b * NN + n) * LL)) * GN + h * DHH;

    // loads (row stride between successive s in q/k/v is NH*DH = 2048)
    for (int i = t; i < 16 * 128; i += 256) {
        int s = i >> 7, d = i & 127;
        sq[s][d] = q[qkv_base + (size_t)s * 2048 + d];
    }
    for (int i = t; i < 4 * 128; i += 256) {
        int j = i >> 7, d = i & 127;
        sk[j][d] = g_kchs[chs_base + (size_t)j * GN + d];
        sv[j][d] = g_vchs[chs_base + (size_t)j * GN + d];
    }
    for (int i = t; i < 16 * 128; i += 256) {
        int s = i >> 7, d = i & 127;
        sk[4 + s][d] = k[qkv_base + (size_t)s * 2048 + d];
        sv[4 + s][d] = v[qkv_base + (size_t)s * 2048 + d];
    }
    __syncthreads();

    // scores: 320 (s,j) pairs
    for (int p = t; p < 320; p += 256) {
        int s = p / 20, j = p % 20;
        float acc = 0.f;
#pragma unroll 8
        for (int d = 0; d < 128; d++) acc += sq[s][d] * sk[j][d];
        sattn[s][j] = acc * ATT_SCALE;
    }
    __syncthreads();

    // softmax per row (20 keys)
    if (t < 16) {
        float mx = -1e30f;
#pragma unroll
        for (int j = 0; j < 20; j++) mx = fmaxf(mx, sattn[t][j]);
        float sum = 0.f;
        float e[20];
#pragma unroll
        for (int j = 0; j < 20; j++) {
            e[j] = expf(sattn[t][j] - mx);
            sum += e[j];
        }
        float inv = 1.f / sum;
#pragma unroll
        for (int j = 0; j < 20; j++) sattn[t][j] = e[j] * inv;
    }
    __syncthreads();

    // out[s][d] = sum_j attn[s][j] * v[j][d]; register-cache v column
    const int d = t & 127;
    const int shalf = t >> 7;
    float vreg[20];
#pragma unroll
    for (int j = 0; j < 20; j++) vreg[j] = sv[j][d];
    const float mval = g_maskf[b * NN + n];
    float* obase = out + ((size_t)(b * (NN * BSQ) + n * BSQ)) * GN + h * DHH + d;
    for (int s = shalf; s < 16; s += 2) {
        float acc = 0.f;
#pragma unroll
        for (int j = 0; j < 20; j++) acc += sattn[s][j] * vreg[j];
        obase[(size_t)s * GN] = acc * mval;
    }
}

// ---------------------------------------------------------------------------
extern "C" void kernel_launch(void* const* d_in, const int* in_sizes, int n_in,
                              void* d_out, int out_size) {
    const float* hs = (const float*)d_in[0];
    const unsigned char* anchors = (const unsigned char*)d_in[1];
    const unsigned char* maskb = (const unsigned char*)d_in[2];
    const float* q = (const float*)d_in[3];
    const float* k = (const float*)d_in[4];
    const float* v = (const float*)d_in[5];
    const float* Wk = (const float*)d_in[6];
    const float* Wv = (const float*)d_in[7];
    float* out = (float*)d_out;

    decode_small_kernel<<<1, 256>>>(anchors, maskb);

    dim3 ggrid(GN / BN, GM / BM, 2);  // 16 x 16 x 2
    gemm_gather_kernel<<<ggrid, 256>>>(hs, Wk, Wv);

    dim3 agrid(NHH, NN, BB);  // 16 x 256 x 2
    attn_kernel<<<agrid, 256>>>(q, k, v, out);
}

// round 9
// speedup vs baseline: 1.1638x; 1.1638x over previous
#include <cuda_runtime.h>
#include <cuda_bf16.h>
#include <math.h>
#include <stdint.h>

// Problem constants
#define LL 4
#define BB 2
#define SS 4096
#define HH 2048
#define NN 256
#define BSQ 16
#define NHH 16
#define DHH 128
// GEMM dims: M = B*N*L = 2048, K = H = 2048, N_out = NH*DH = 2048
#define GM 2048
#define GK 2048
#define GN 2048
#define BM 128
#define BN 128
#define BKK 32

#define APAD 36    // A row pitch (floats), 16B-aligned, conflict-free frag loads
#define BPAD 132   // B row pitch (floats), 16B-aligned
#define A_ELEMS (BM * APAD)        // 4608
#define B_ELEMS (BKK * BPAD)       // 4224
#define STAGE_ELEMS (A_ELEMS + B_ELEMS)  // 8832 floats = 34.5 KB
#define GEMM_SMEM_BYTES (2 * STAGE_ELEMS * 4)  // 70656

#define ATT_SCALE 0.08838834764831843f  // 1/sqrt(128)

// Scratch for projected context K/V: (B*N*L) x (NH*DH) f32, 16 MB each
__device__ float g_kchs[(size_t)GM * GN];
__device__ float g_vchs[(size_t)GM * GN];
// Decoded context indices + mask
__device__ int g_ctx[BB * NN];
__device__ float g_maskf[BB * NN];

__device__ __forceinline__ void mma_tf32(float c[4], uint32_t a0, uint32_t a1,
                                         uint32_t a2, uint32_t a3,
                                         uint32_t b0, uint32_t b1) {
    asm volatile(
        "mma.sync.aligned.m16n8k8.row.col.f32.tf32.tf32.f32 "
        "{%0,%1,%2,%3}, {%4,%5,%6,%7}, {%8,%9}, {%0,%1,%2,%3};\n"
        : "+f"(c[0]), "+f"(c[1]), "+f"(c[2]), "+f"(c[3])
        : "r"(a0), "r"(a1), "r"(a2), "r"(a3), "r"(b0), "r"(b1));
}

__device__ __forceinline__ void cp_async16(float* dst_smem, const float* src) {
    uint32_t d = (uint32_t)__cvta_generic_to_shared(dst_smem);
    asm volatile("cp.async.cg.shared.global [%0], [%1], 16;\n" ::"r"(d),
                 "l"(src));
}

// ---------------------------------------------------------------------------
// Decode anchors (d_in[1], int32-or-int64 sniff) and mask (d_in[2],
// int32-or-int8 sniff). All sniffs read only the first 512 bytes of each
// buffer (in-bounds under every dtype hypothesis).
// ---------------------------------------------------------------------------
__global__ void decode_small_kernel(const unsigned char* __restrict__ anc_b,
                                    const unsigned char* __restrict__ msk_b) {
    __shared__ int is32flag, maskPacked;
    if (threadIdx.x == 0) { is32flag = 0; maskPacked = 0; }
    __syncthreads();

    const long long* a64 = (const long long*)anc_b;
    const int* a32 = (const int*)anc_b;
    for (int i = threadIdx.x; i < 64; i += blockDim.x) {
        if ((a64[i] >> 32) != 0) atomicOr(&is32flag, 1);
    }
    const unsigned int* m32 = (const unsigned int*)msk_b;
    for (int i = threadIdx.x; i < 128; i += blockDim.x) {
        if (m32[i] > 1u) atomicOr(&maskPacked, 1);  // packed int8 bools
    }
    __syncthreads();
    const int is32 = is32flag;
    const int mpack = maskPacked;
    for (int i = threadIdx.x; i < BB * NN; i += blockDim.x) {
        int a = is32 ? a32[i] : (int)a64[i];
        int ctx = a - 1;
        if (ctx < 0) ctx = 0;
        g_ctx[i] = ctx;
        unsigned int mv = mpack ? (unsigned int)msk_b[i] : m32[i];
        g_maskf[i] = mv ? 1.f : 0.f;
    }
}

// ---------------------------------------------------------------------------
// GEMM with fused gather, cp.async 2-stage pipeline.
//   out[m, n] = sum_k hs_row(m)[k] * W[k, n]
//   m = (b*N + n_blk)*L + l ; hs_row base = ((l*B + b)*S + ctx[b,n_blk]) * H
// gridDim = (GN/BN, GM/BM, 2) ; z=0 -> W_kc -> g_kchs, z=1 -> W_vc -> g_vchs
// fp32 bits fed directly to tf32 MMA (hardware truncation).
// ---------------------------------------------------------------------------
__global__ __launch_bounds__(256)
void gemm_gather_kernel(const float* __restrict__ hs,
                        const float* __restrict__ Wk,
                        const float* __restrict__ Wv) {
    extern __shared__ float dsm[];
    __shared__ int rowoff[BM];

    const int t = threadIdx.x;
    const int m0 = blockIdx.y * BM;
    const int n0 = blockIdx.x * BN;
    const float* __restrict__ W = (blockIdx.z == 0) ? Wk : Wv;
    float* __restrict__ dst = (blockIdx.z == 0) ? g_kchs : g_vchs;

    if (t < BM) {
        int m = m0 + t;
        int b = m >> 10;           // / (N*L)=1024
        int rem = m & 1023;
        int nb = rem >> 2;         // / L
        int l = rem & 3;
        int ctx = g_ctx[b * NN + nb];
        rowoff[t] = ((l * BB + b) * SS + ctx) * HH;
    }
    __syncthreads();

    const int lane = t & 31;
    const int wid = t >> 5;
    const int wm = wid >> 1;   // 0..3
    const int wn = wid & 1;    // 0..1
    const int qr = lane >> 2;  // 0..7
    const int qc = lane & 3;   // 0..3

    // Per-thread load coordinates (stage-invariant)
    const int arow = t >> 3;            // 0..31 (+32p)
    const int acg = (t & 7) * 4;        // 0..28
    const int brow = t >> 5;            // 0..7 (+8p)
    const int bcg = (t & 31) * 4;       // 0..124

    float acc[2][8][4];
#pragma unroll
    for (int mt = 0; mt < 2; mt++)
#pragma unroll
        for (int nt = 0; nt < 8; nt++)
#pragma unroll
            for (int i = 0; i < 4; i++) acc[mt][nt][i] = 0.f;

    // Prologue: issue stage 0
    {
        float* As = dsm;
        float* Bs = dsm + A_ELEMS;
#pragma unroll
        for (int p = 0; p < 4; p++) {
            int row = arow + p * 32;
            cp_async16(As + row * APAD + acg, hs + (size_t)rowoff[row] + acg);
        }
#pragma unroll
        for (int p = 0; p < 4; p++) {
            int row = brow + p * 8;
            cp_async16(Bs + row * BPAD + bcg,
                       W + (size_t)row * GN + n0 + bcg);
        }
        asm volatile("cp.async.commit_group;\n" ::: "memory");
    }

    const int NIT = GK / BKK;  // 64
    for (int it = 0; it < NIT; it++) {
        const int s = it & 1;
        // Issue next stage into the other buffer (prev MMA reads of that
        // buffer were fenced by the loop-end __syncthreads)
        if (it + 1 < NIT) {
            const int k0n = (it + 1) * BKK;
            float* As = dsm + (s ^ 1) * STAGE_ELEMS;
            float* Bs = As + A_ELEMS;
#pragma unroll
            for (int p = 0; p < 4; p++) {
                int row = arow + p * 32;
                cp_async16(As + row * APAD + acg,
                           hs + (size_t)rowoff[row] + k0n + acg);
            }
#pragma unroll
            for (int p = 0; p < 4; p++) {
                int row = brow + p * 8;
                cp_async16(Bs + row * BPAD + bcg,
                           W + (size_t)(k0n + row) * GN + n0 + bcg);
            }
            asm volatile("cp.async.commit_group;\n" ::: "memory");
            asm volatile("cp.async.wait_group 1;\n" ::: "memory");
        } else {
            asm volatile("cp.async.wait_group 0;\n" ::: "memory");
        }
        __syncthreads();

        const uint32_t* As = (const uint32_t*)(dsm + s * STAGE_ELEMS);
        const uint32_t* Bs = As + A_ELEMS;

#pragma unroll
        for (int ks = 0; ks < 4; ks++) {
            uint32_t afr[2][4];
            uint32_t bfr[8][2];
#pragma unroll
            for (int mt = 0; mt < 2; mt++) {
                int rb = wm * 32 + mt * 16;
                afr[mt][0] = As[(rb + qr) * APAD + ks * 8 + qc];
                afr[mt][1] = As[(rb + qr + 8) * APAD + ks * 8 + qc];
                afr[mt][2] = As[(rb + qr) * APAD + ks * 8 + qc + 4];
                afr[mt][3] = As[(rb + qr + 8) * APAD + ks * 8 + qc + 4];
            }
#pragma unroll
            for (int nt = 0; nt < 8; nt++) {
                int col = wn * 64 + nt * 8 + qr;
                bfr[nt][0] = Bs[(ks * 8 + qc) * BPAD + col];
                bfr[nt][1] = Bs[(ks * 8 + qc + 4) * BPAD + col];
            }
#pragma unroll
            for (int mt = 0; mt < 2; mt++)
#pragma unroll
                for (int nt = 0; nt < 8; nt++)
                    mma_tf32(acc[mt][nt], afr[mt][0], afr[mt][1], afr[mt][2],
                             afr[mt][3], bfr[nt][0], bfr[nt][1]);
        }
        __syncthreads();
    }

    // Epilogue
#pragma unroll
    for (int mt = 0; mt < 2; mt++) {
#pragma unroll
        for (int nt = 0; nt < 8; nt++) {
            int r0 = m0 + wm * 32 + mt * 16 + qr;
            int c0 = n0 + wn * 64 + nt * 8 + 2 * qc;
            *(float2*)(dst + (size_t)r0 * GN + c0) =
                make_float2(acc[mt][nt][0], acc[mt][nt][1]);
            *(float2*)(dst + (size_t)(r0 + 8) * GN + c0) =
                make_float2(acc[mt][nt][2], acc[mt][nt][3]);
        }
    }
}

// ---------------------------------------------------------------------------
// Attention: one block per (h, n, b). 16 queries x 20 keys x 128 dims.
// keys/values = [4 projected context rows] ++ [16 block rows].
// ---------------------------------------------------------------------------
#define SKP 132

__global__ __launch_bounds__(256)
void attn_kernel(const float* __restrict__ q, const float* __restrict__ k,
                 const float* __restrict__ v,
                 float* __restrict__ out) {
    __shared__ float sq[16][SKP];
    __shared__ float sk[20][SKP];
    __shared__ float sv[20][SKP];
    __shared__ float sattn[16][20];

    const int t = threadIdx.x;
    const int h = blockIdx.x;
    const int n = blockIdx.y;
    const int b = blockIdx.z;

    const size_t qkv_base = (((size_t)(b * (NN * BSQ) + n * BSQ)) * NHH + h) * DHH;
    const size_t chs_base = ((size_t)((b * NN + n) * LL)) * GN + h * DHH;

    // Vectorized loads (all bases are 128-float aligned)
    for (int i = t; i < 16 * 32; i += 256) {
        int s = i >> 5, dq = i & 31;
        *(float4*)&sq[s][dq * 4] =
            *(const float4*)(q + qkv_base + (size_t)s * 2048 + dq * 4);
    }
    for (int i = t; i < 4 * 32; i += 256) {
        int j = i >> 5, dq = i & 31;
        *(float4*)&sk[j][dq * 4] =
            *(const float4*)(g_kchs + chs_base + (size_t)j * GN + dq * 4);
        *(float4*)&sv[j][dq * 4] =
            *(const float4*)(g_vchs + chs_base + (size_t)j * GN + dq * 4);
    }
    for (int i = t; i < 16 * 32; i += 256) {
        int s = i >> 5, dq = i & 31;
        *(float4*)&sk[4 + s][dq * 4] =
            *(const float4*)(k + qkv_base + (size_t)s * 2048 + dq * 4);
        *(float4*)&sv[4 + s][dq * 4] =
            *(const float4*)(v + qkv_base + (size_t)s * 2048 + dq * 4);
    }
    __syncthreads();

    // scores: 320 (s,j) pairs, float4 smem reads
    for (int p = t; p < 320; p += 256) {
        int s = p / 20, j = p % 20;
        const float4* qrow = (const float4*)&sq[s][0];
        const float4* krow = (const float4*)&sk[j][0];
        float acc = 0.f;
#pragma unroll 8
        for (int dq = 0; dq < 32; dq++) {
            float4 a = qrow[dq];
            float4 c = krow[dq];
            acc += a.x * c.x + a.y * c.y + a.z * c.z + a.w * c.w;
        }
        sattn[s][j] = acc * ATT_SCALE;
    }
    __syncthreads();

    // softmax per row (20 keys)
    if (t < 16) {
        float mx = -1e30f;
#pragma unroll
        for (int j = 0; j < 20; j++) mx = fmaxf(mx, sattn[t][j]);
        float sum = 0.f;
        float e[20];
#pragma unroll
        for (int j = 0; j < 20; j++) {
            e[j] = expf(sattn[t][j] - mx);
            sum += e[j];
        }
        float inv = 1.f / sum;
#pragma unroll
        for (int j = 0; j < 20; j++) sattn[t][j] = e[j] * inv;
    }
    __syncthreads();

    // out[s][d] = sum_j attn[s][j] * v[j][d]; register-cache v column
    const int d = t & 127;
    const int shalf = t >> 7;
    float vreg[20];
#pragma unroll
    for (int j = 0; j < 20; j++) vreg[j] = sv[j][d];
    const float mval = g_maskf[b * NN + n];
    float* obase = out + ((size_t)(b * (NN * BSQ) + n * BSQ)) * GN + h * DHH + d;
    for (int s = shalf; s < 16; s += 2) {
        float acc = 0.f;
#pragma unroll
        for (int j = 0; j < 20; j++) acc += sattn[s][j] * vreg[j];
        obase[(size_t)s * GN] = acc * mval;
    }
}

// ---------------------------------------------------------------------------
extern "C" void kernel_launch(void* const* d_in, const int* in_sizes, int n_in,
                              void* d_out, int out_size) {
    const float* hs = (const float*)d_in[0];
    const unsigned char* anchors = (const unsigned char*)d_in[1];
    const unsigned char* maskb = (const unsigned char*)d_in[2];
    const float* q = (const float*)d_in[3];
    const float* k = (const float*)d_in[4];
    const float* v = (const float*)d_in[5];
    const float* Wk = (const float*)d_in[6];
    const float* Wv = (const float*)d_in[7];
    float* out = (float*)d_out;

    cudaFuncSetAttribute(gemm_gather_kernel,
                         cudaFuncAttributeMaxDynamicSharedMemorySize,
                         GEMM_SMEM_BYTES);

    decode_small_kernel<<<1, 256>>>(anchors, maskb);

    dim3 ggrid(GN / BN, GM / BM, 2);  // 16 x 16 x 2
    gemm_gather_kernel<<<ggrid, 256, GEMM_SMEM_BYTES>>>(hs, Wk, Wv);

    dim3 agrid(NHH, NN, BB);  // 16 x 256 x 2
    attn_kernel<<<agrid, 256>>>(q, k, v, out);
}

// round 13
// speedup vs baseline: 2.5123x; 2.1588x over previous
#include <cuda_runtime.h>
#include <cuda_fp16.h>
#include <math.h>
#include <stdint.h>

// Problem constants
#define LL 4
#define BB 2
#define SS 4096
#define HH 2048
#define NN 256
#define BSQ 16
#define NHH 16
#define DHH 128
#define GM 2048
#define GK 2048
#define GN 2048

// fp16 GEMM tiling
#define BM 128
#define BN 128
#define BKK 64                        // k per stage tile (64 fp16 = 128B rows)
#define NKT (GK / BKK)                // 32 k-tiles
#define PITCH32 36                    // b32 per smem row (32 data + 4 pad)
#define TILE_BYTES (128 * PITCH32 * 4)        // 18432
#define STAGE_BYTES (2 * TILE_BYTES)          // 36864 (A tile + B tile)
#define GEMM_DSMEM (2 * STAGE_BYTES)          // 73728

#define ATT_SCALE 0.08838834764831843f  // 1/sqrt(128)

// Device scratch
__device__ float g_kchs[(size_t)GM * GN];
__device__ float g_vchs[(size_t)GM * GN];
__device__ __half g_ah[(size_t)GM * GK];    // gathered A, fp16 rna
__device__ __half g_wkt[(size_t)GN * GK];   // Wk^T [n][k] fp16 rna
__device__ __half g_wvt[(size_t)GN * GK];   // Wv^T [n][k] fp16 rna
__device__ int g_ctx[BB * NN];
__device__ float g_maskf[BB * NN];

__device__ __forceinline__ void mma_f16(float c[4], uint32_t a0, uint32_t a1,
                                        uint32_t a2, uint32_t a3,
                                        uint32_t b0, uint32_t b1) {
    asm volatile(
        "mma.sync.aligned.m16n8k16.row.col.f32.f16.f16.f32 "
        "{%0,%1,%2,%3}, {%4,%5,%6,%7}, {%8,%9}, {%0,%1,%2,%3};\n"
        : "+f"(c[0]), "+f"(c[1]), "+f"(c[2]), "+f"(c[3])
        : "r"(a0), "r"(a1), "r"(a2), "r"(a3), "r"(b0), "r"(b1));
}

__device__ __forceinline__ void cp_async16(uint32_t dst_smem, const void* src) {
    asm volatile("cp.async.cg.shared.global [%0], [%1], 16;\n" ::"r"(dst_smem),
                 "l"(src));
}

// ---------------------------------------------------------------------------
// Decode anchors (int32/int64 sniff) + mask (int32/int8 sniff). All sniffs
// read only the first 512 bytes of each buffer.
// ---------------------------------------------------------------------------
__global__ void decode_small_kernel(const unsigned char* __restrict__ anc_b,
                                    const unsigned char* __restrict__ msk_b) {
    __shared__ int is32flag, maskPacked;
    if (threadIdx.x == 0) { is32flag = 0; maskPacked = 0; }
    __syncthreads();

    const long long* a64 = (const long long*)anc_b;
    const int* a32 = (const int*)anc_b;
    for (int i = threadIdx.x; i < 64; i += blockDim.x) {
        if ((a64[i] >> 32) != 0) atomicOr(&is32flag, 1);
    }
    const unsigned int* m32 = (const unsigned int*)msk_b;
    for (int i = threadIdx.x; i < 128; i += blockDim.x) {
        if (m32[i] > 1u) atomicOr(&maskPacked, 1);
    }
    __syncthreads();
    const int is32 = is32flag;
    const int mpack = maskPacked;
    for (int i = threadIdx.x; i < BB * NN; i += blockDim.x) {
        int a = is32 ? a32[i] : (int)a64[i];
        int ctx = a - 1;
        if (ctx < 0) ctx = 0;
        g_ctx[i] = ctx;
        unsigned int mv = mpack ? (unsigned int)msk_b[i] : m32[i];
        g_maskf[i] = mv ? 1.f : 0.f;
    }
}

// ---------------------------------------------------------------------------
// Gather hs rows -> dense fp16 (rna) A buffer.
// m = (b*N + nb)*L + l ; src row = (l*B + b)*S + ctx[b,nb]
// ---------------------------------------------------------------------------
__global__ __launch_bounds__(256)
void gather_f16_kernel(const float* __restrict__ hs) {
    int idx = blockIdx.x * 256 + threadIdx.x;  // m*512 + c4
    int m = idx >> 9;
    int c4 = idx & 511;
    int b = m >> 10, rem = m & 1023, nb = rem >> 2, l = rem & 3;
    int ctx = g_ctx[b * NN + nb];
    const float4 f =
        *(const float4*)(hs + ((size_t)((l * BB + b) * SS + ctx)) * HH + c4 * 4);
    __half2 h0 = make_half2(__float2half_rn(f.x), __float2half_rn(f.y));
    __half2 h1 = make_half2(__float2half_rn(f.z), __float2half_rn(f.w));
    *(__half2*)(g_ah + (size_t)m * GK + c4 * 4) = h0;
    *(__half2*)(g_ah + (size_t)m * GK + c4 * 4 + 2) = h1;
}

// ---------------------------------------------------------------------------
// Transpose W[k][n] -> Wt[n][k] fp16 (rna), both weights (z).
// ---------------------------------------------------------------------------
__global__ __launch_bounds__(256)
void transpose_f16_kernel(const float* __restrict__ Wk,
                          const float* __restrict__ Wv) {
    __shared__ float ts[32][33];
    const float* __restrict__ W = blockIdx.z ? Wv : Wk;
    __half* __restrict__ Wt = blockIdx.z ? g_wvt : g_wkt;
    int k0 = blockIdx.y * 32, n0 = blockIdx.x * 32;
    int tx = threadIdx.x & 31, ty8 = threadIdx.x >> 5;
#pragma unroll
    for (int p = 0; p < 4; p++) {
        int ty = ty8 + p * 8;
        ts[ty][tx] = W[(size_t)(k0 + ty) * GN + n0 + tx];
    }
    __syncthreads();
#pragma unroll
    for (int p = 0; p < 4; p++) {
        int ty = ty8 + p * 8;
        Wt[(size_t)(n0 + ty) * GK + k0 + tx] = __float2half_rn(ts[tx][ty]);
    }
}

// ---------------------------------------------------------------------------
// fp16 m16n8k16 GEMM, 2-stage cp.async pipeline, conflict-free smem.
//   dst[m][n] = sum_k A[m][k] * Wt[n][k]
// grid (16, 16, 2): z=0 -> g_kchs (Wkt), z=1 -> g_vchs (Wvt)
// Smem row: 64 fp16 (128B data) at pitch 36 b32 (144B).
// ---------------------------------------------------------------------------
__global__ __launch_bounds__(256)
void gemm_f16_kernel() {
    extern __shared__ unsigned char dyn_smem[];
    const int t = threadIdx.x;
    const int m0 = blockIdx.y * BM;
    const int n0 = blockIdx.x * BN;
    const __half* __restrict__ Bt = (blockIdx.z == 0) ? g_wkt : g_wvt;
    float* __restrict__ dst = (blockIdx.z == 0) ? g_kchs : g_vchs;

    const uint32_t sbase = (uint32_t)__cvta_generic_to_shared(dyn_smem);

    const int lane = t & 31;
    const int wid = t >> 5;
    const int wm = wid >> 1;   // 0..3
    const int wn = wid & 1;    // 0..1
    const int qr = lane >> 2;  // 0..7
    const int qc = lane & 3;   // 0..3

    // cp.async mapping: 8 chunks/thread/stage, 128B coalesced rows.
    const int ld_row = t >> 3;   // 0..31 (+32 per p&3)
    const int ld_part = t & 7;   // 16B offset in 128B row

    float acc[2][8][4];
#pragma unroll
    for (int mt = 0; mt < 2; mt++)
#pragma unroll
        for (int nt = 0; nt < 8; nt++)
#pragma unroll
            for (int i = 0; i < 4; i++) acc[mt][nt][i] = 0.f;

#define LOAD_STAGE(SB, K0)                                                     \
    do {                                                                       \
        _Pragma("unroll") for (int p = 0; p < 8; p++) {                        \
            const int mat = p >> 2;                                           \
            const int row = ((p & 3) << 5) + ld_row;                          \
            const __half* src = (mat == 0)                                     \
                ? g_ah + (size_t)(m0 + row) * GK + (K0) + ld_part * 8          \
                : Bt + (size_t)(n0 + row) * GK + (K0) + ld_part * 8;           \
            cp_async16((SB) + mat * TILE_BYTES + row * (PITCH32 * 4) +         \
                           ld_part * 16,                                       \
                       src);                                                   \
        }                                                                      \
        asm volatile("cp.async.commit_group;" ::: "memory");                   \
    } while (0)

    LOAD_STAGE(sbase, 0);

    for (int it = 0; it < NKT; it++) {
        const uint32_t scur = sbase + (it & 1) * STAGE_BYTES;
        const uint32_t snxt = sbase + ((it & 1) ^ 1) * STAGE_BYTES;
        if (it + 1 < NKT) {
            LOAD_STAGE(snxt, (it + 1) * BKK);
            asm volatile("cp.async.wait_group 1;" ::: "memory");
        } else {
            asm volatile("cp.async.wait_group 0;" ::: "memory");
        }
        __syncthreads();

        // b32 views of current stage
        const uint32_t* As;
        const uint32_t* Bs;
        {
            // reconstruct generic pointers from shared offsets
            As = (const uint32_t*)(dyn_smem + (it & 1) * STAGE_BYTES);
            Bs = (const uint32_t*)(dyn_smem + (it & 1) * STAGE_BYTES + TILE_BYTES);
        }

#pragma unroll
        for (int ks = 0; ks < 4; ks++) {  // 4 x k16 per 64-k tile
            uint32_t afr[2][4];
#pragma unroll
            for (int mt = 0; mt < 2; mt++) {
                const int rb = wm * 32 + mt * 16;
                afr[mt][0] = As[(rb + qr) * PITCH32 + ks * 8 + qc];
                afr[mt][1] = As[(rb + qr + 8) * PITCH32 + ks * 8 + qc];
                afr[mt][2] = As[(rb + qr) * PITCH32 + ks * 8 + qc + 4];
                afr[mt][3] = As[(rb + qr + 8) * PITCH32 + ks * 8 + qc + 4];
            }
#pragma unroll
            for (int nt = 0; nt < 8; nt++) {
                const int col = wn * 64 + nt * 8 + qr;
                uint32_t b0 = Bs[col * PITCH32 + ks * 8 + qc];
                uint32_t b1 = Bs[col * PITCH32 + ks * 8 + qc + 4];
#pragma unroll
                for (int mt = 0; mt < 2; mt++)
                    mma_f16(acc[mt][nt], afr[mt][0], afr[mt][1], afr[mt][2],
                            afr[mt][3], b0, b1);
            }
        }
        __syncthreads();
    }

    // Epilogue
#pragma unroll
    for (int mt = 0; mt < 2; mt++) {
#pragma unroll
        for (int nt = 0; nt < 8; nt++) {
            int r0 = m0 + wm * 32 + mt * 16 + qr;
            int c0 = n0 + wn * 64 + nt * 8 + 2 * qc;
            *(float2*)(dst + (size_t)r0 * GN + c0) =
                make_float2(acc[mt][nt][0], acc[mt][nt][1]);
            *(float2*)(dst + (size_t)(r0 + 8) * GN + c0) =
                make_float2(acc[mt][nt][2], acc[mt][nt][3]);
        }
    }
#undef LOAD_STAGE
}

// ---------------------------------------------------------------------------
// Attention: one block per (h, n, b). 16 queries x 20 keys x 128 dims.
// ---------------------------------------------------------------------------
#define SKP 132

__global__ __launch_bounds__(256)
void attn_kernel(const float* __restrict__ q, const float* __restrict__ k,
                 const float* __restrict__ v,
                 float* __restrict__ out) {
    __shared__ float sq[16][SKP];
    __shared__ float sk[20][SKP];
    __shared__ float sv[20][SKP];
    __shared__ float sattn[16][20];

    const int t = threadIdx.x;
    const int h = blockIdx.x;
    const int n = blockIdx.y;
    const int b = blockIdx.z;

    const size_t qkv_base = (((size_t)(b * (NN * BSQ) + n * BSQ)) * NHH + h) * DHH;
    const size_t chs_base = ((size_t)((b * NN + n) * LL)) * GN + h * DHH;

    for (int i = t; i < 16 * 32; i += 256) {
        int s = i >> 5, dq = i & 31;
        *(float4*)&sq[s][dq * 4] =
            *(const float4*)(q + qkv_base + (size_t)s * 2048 + dq * 4);
    }
    for (int i = t; i < 4 * 32; i += 256) {
        int j = i >> 5, dq = i & 31;
        *(float4*)&sk[j][dq * 4] =
            *(const float4*)(g_kchs + chs_base + (size_t)j * GN + dq * 4);
        *(float4*)&sv[j][dq * 4] =
            *(const float4*)(g_vchs + chs_base + (size_t)j * GN + dq * 4);
    }
    for (int i = t; i < 16 * 32; i += 256) {
        int s = i >> 5, dq = i & 31;
        *(float4*)&sk[4 + s][dq * 4] =
            *(const float4*)(k + qkv_base + (size_t)s * 2048 + dq * 4);
        *(float4*)&sv[4 + s][dq * 4] =
            *(const float4*)(v + qkv_base + (size_t)s * 2048 + dq * 4);
    }
    __syncthreads();

    for (int p = t; p < 320; p += 256) {
        int s = p / 20, j = p % 20;
        const float4* qrow = (const float4*)&sq[s][0];
        const float4* krow = (const float4*)&sk[j][0];
        float acc = 0.f;
#pragma unroll 8
        for (int dq = 0; dq < 32; dq++) {
            float4 a = qrow[dq];
            float4 c = krow[dq];
            acc += a.x * c.x + a.y * c.y + a.z * c.z + a.w * c.w;
        }
        sattn[s][j] = acc * ATT_SCALE;
    }
    __syncthreads();

    if (t < 16) {
        float mx = -1e30f;
#pragma unroll
        for (int j = 0; j < 20; j++) mx = fmaxf(mx, sattn[t][j]);
        float sum = 0.f;
        float e[20];
#pragma unroll
        for (int j = 0; j < 20; j++) {
            e[j] = expf(sattn[t][j] - mx);
            sum += e[j];
        }
        float inv = 1.f / sum;
#pragma unroll
        for (int j = 0; j < 20; j++) sattn[t][j] = e[j] * inv;
    }
    __syncthreads();

    const int d = t & 127;
    const int shalf = t >> 7;
    float vreg[20];
#pragma unroll
    for (int j = 0; j < 20; j++) vreg[j] = sv[j][d];
    const float mval = g_maskf[b * NN + n];
    float* obase = out + ((size_t)(b * (NN * BSQ) + n * BSQ)) * GN + h * DHH + d;
    for (int s = shalf; s < 16; s += 2) {
        float acc = 0.f;
#pragma unroll
        for (int j = 0; j < 20; j++) acc += sattn[s][j] * vreg[j];
        obase[(size_t)s * GN] = acc * mval;
    }
}

// ---------------------------------------------------------------------------
extern "C" void kernel_launch(void* const* d_in, const int* in_sizes, int n_in,
                              void* d_out, int out_size) {
    const float* hs = (const float*)d_in[0];
    const unsigned char* anchors = (const unsigned char*)d_in[1];
    const unsigned char* maskb = (const unsigned char*)d_in[2];
    const float* q = (const float*)d_in[3];
    const float* k = (const float*)d_in[4];
    const float* v = (const float*)d_in[5];
    const float* Wk = (const float*)d_in[6];
    const float* Wv = (const float*)d_in[7];
    float* out = (float*)d_out;

    cudaFuncSetAttribute(gemm_f16_kernel,
                         cudaFuncAttributeMaxDynamicSharedMemorySize,
                         GEMM_DSMEM);

    decode_small_kernel<<<1, 256>>>(anchors, maskb);
    gather_f16_kernel<<<4096, 256>>>(hs);
    transpose_f16_kernel<<<dim3(64, 64, 2), 256>>>(Wk, Wv);

    gemm_f16_kernel<<<dim3(GN / BN, GM / BM, 2), 256, GEMM_DSMEM>>>();

    dim3 agrid(NHH, NN, BB);  // 16 x 256 x 2
    attn_kernel<<<agrid, 256>>>(q, k, v, out);
}

// round 17
// speedup vs baseline: 2.6140x; 1.0405x over previous
#include <cuda_runtime.h>
#include <cuda_fp16.h>
#include <math.h>
#include <stdint.h>

// Problem constants
#define LL 4
#define BB 2
#define SS 4096
#define HH 2048
#define NN 256
#define BSQ 16
#define NHH 16
#define DHH 128
#define GM 2048
#define GK 2048
#define GN 2048

// fp16 GEMM tiling
#define BM 128
#define BN 128
#define BKK 64                        // k per stage tile (64 fp16 = 128B rows)
#define NKT (GK / BKK)                // 32 k-tiles
#define PITCH32 36                    // b32 per smem row (32 data + 4 pad)
#define PITCHB (PITCH32 * 4)          // 144 bytes
#define TILE_BYTES (128 * PITCHB)     // 18432
#define STAGE_BYTES (2 * TILE_BYTES)  // 36864 (A tile + B tile)
#define GEMM_DSMEM (2 * STAGE_BYTES)  // 73728

#define ATT_SCALE 0.08838834764831843f  // 1/sqrt(128)

// Device scratch
__device__ float g_kchs[(size_t)GM * GN];
__device__ float g_vchs[(size_t)GM * GN];
__device__ __half g_ah[(size_t)GM * GK];    // gathered A, fp16 rna
__device__ __half g_wkt[(size_t)GN * GK];   // Wk^T [n][k] fp16 rna
__device__ __half g_wvt[(size_t)GN * GK];   // Wv^T [n][k] fp16 rna
__device__ int g_ctx[BB * NN];
__device__ float g_maskf[BB * NN];

__device__ __forceinline__ void mma_f16(float c[4], uint32_t a0, uint32_t a1,
                                        uint32_t a2, uint32_t a3,
                                        uint32_t b0, uint32_t b1) {
    asm volatile(
        "mma.sync.aligned.m16n8k16.row.col.f32.f16.f16.f32 "
        "{%0,%1,%2,%3}, {%4,%5,%6,%7}, {%8,%9}, {%0,%1,%2,%3};\n"
        : "+f"(c[0]), "+f"(c[1]), "+f"(c[2]), "+f"(c[3])
        : "r"(a0), "r"(a1), "r"(a2), "r"(a3), "r"(b0), "r"(b1));
}

__device__ __forceinline__ void ldmx4(uint32_t r[4], uint32_t saddr) {
    asm volatile(
        "ldmatrix.sync.aligned.m8n8.x4.shared.b16 {%0,%1,%2,%3}, [%4];\n"
        : "=r"(r[0]), "=r"(r[1]), "=r"(r[2]), "=r"(r[3])
        : "r"(saddr));
}

__device__ __forceinline__ void cp_async16(uint32_t dst_smem, const void* src) {
    asm volatile("cp.async.cg.shared.global [%0], [%1], 16;\n" ::"r"(dst_smem),
                 "l"(src));
}

// ---------------------------------------------------------------------------
// Decode anchors (int32/int64 sniff) + mask (int32/int8 sniff). All sniffs
// read only the first 512 bytes of each buffer.
// ---------------------------------------------------------------------------
__global__ void decode_small_kernel(const unsigned char* __restrict__ anc_b,
                                    const unsigned char* __restrict__ msk_b) {
    __shared__ int is32flag, maskPacked;
    if (threadIdx.x == 0) { is32flag = 0; maskPacked = 0; }
    __syncthreads();

    const long long* a64 = (const long long*)anc_b;
    const int* a32 = (const int*)anc_b;
    for (int i = threadIdx.x; i < 64; i += blockDim.x) {
        if ((a64[i] >> 32) != 0) atomicOr(&is32flag, 1);
    }
    const unsigned int* m32 = (const unsigned int*)msk_b;
    for (int i = threadIdx.x; i < 128; i += blockDim.x) {
        if (m32[i] > 1u) atomicOr(&maskPacked, 1);
    }
    __syncthreads();
    const int is32 = is32flag;
    const int mpack = maskPacked;
    for (int i = threadIdx.x; i < BB * NN; i += blockDim.x) {
        int a = is32 ? a32[i] : (int)a64[i];
        int ctx = a - 1;
        if (ctx < 0) ctx = 0;
        g_ctx[i] = ctx;
        unsigned int mv = mpack ? (unsigned int)msk_b[i] : m32[i];
        g_maskf[i] = mv ? 1.f : 0.f;
    }
}

// ---------------------------------------------------------------------------
// Gather hs rows -> dense fp16 (rna) A buffer.
// ---------------------------------------------------------------------------
__global__ __launch_bounds__(256)
void gather_f16_kernel(const float* __restrict__ hs) {
    int idx = blockIdx.x * 256 + threadIdx.x;  // m*512 + c4
    int m = idx >> 9;
    int c4 = idx & 511;
    int b = m >> 10, rem = m & 1023, nb = rem >> 2, l = rem & 3;
    int ctx = g_ctx[b * NN + nb];
    const float4 f =
        *(const float4*)(hs + ((size_t)((l * BB + b) * SS + ctx)) * HH + c4 * 4);
    __half2 h0 = make_half2(__float2half_rn(f.x), __float2half_rn(f.y));
    __half2 h1 = make_half2(__float2half_rn(f.z), __float2half_rn(f.w));
    *(__half2*)(g_ah + (size_t)m * GK + c4 * 4) = h0;
    *(__half2*)(g_ah + (size_t)m * GK + c4 * 4 + 2) = h1;
}

// ---------------------------------------------------------------------------
// Transpose W[k][n] -> Wt[n][k] fp16 (rna), both weights (z).
// ---------------------------------------------------------------------------
__global__ __launch_bounds__(256)
void transpose_f16_kernel(const float* __restrict__ Wk,
                          const float* __restrict__ Wv) {
    __shared__ float ts[32][33];
    const float* __restrict__ W = blockIdx.z ? Wv : Wk;
    __half* __restrict__ Wt = blockIdx.z ? g_wvt : g_wkt;
    int k0 = blockIdx.y * 32, n0 = blockIdx.x * 32;
    int tx = threadIdx.x & 31, ty8 = threadIdx.x >> 5;
#pragma unroll
    for (int p = 0; p < 4; p++) {
        int ty = ty8 + p * 8;
        ts[ty][tx] = W[(size_t)(k0 + ty) * GN + n0 + tx];
    }
    __syncthreads();
#pragma unroll
    for (int p = 0; p < 4; p++) {
        int ty = ty8 + p * 8;
        Wt[(size_t)(n0 + ty) * GK + k0 + tx] = __float2half_rn(ts[tx][ty]);
    }
}

// ---------------------------------------------------------------------------
// fp16 m16n8k16 GEMM, 2-stage cp.async pipeline, ldmatrix fragment loads.
//   dst[m][n] = sum_k A[m][k] * Wt[n][k]
// grid (16, 16, 2): z=0 -> g_kchs (Wkt), z=1 -> g_vchs (Wvt)
// ---------------------------------------------------------------------------
__global__ __launch_bounds__(256)
void gemm_f16_kernel() {
    extern __shared__ unsigned char dyn_smem[];
    const int t = threadIdx.x;
    const int m0 = blockIdx.y * BM;
    const int n0 = blockIdx.x * BN;
    const __half* __restrict__ Bt = (blockIdx.z == 0) ? g_wkt : g_wvt;
    float* __restrict__ dst = (blockIdx.z == 0) ? g_kchs : g_vchs;

    const uint32_t sbase = (uint32_t)__cvta_generic_to_shared(dyn_smem);

    const int lane = t & 31;
    const int wid = t >> 5;
    const int wm = wid >> 1;   // 0..3
    const int wn = wid & 1;    // 0..1
    const int qr = lane >> 2;  // 0..7
    const int qc = lane & 3;   // 0..3

    // ldmatrix lane address components
    const int g8 = lane >> 3;   // matrix group 0..3
    const int l8 = lane & 7;    // row within matrix
    // A: mat g -> row (g&1)*8, col-bytes (g>>1)*16
    const uint32_t a_lane_off =
        (uint32_t)((wm * 32 + ((g8 & 1) << 3) + l8) * PITCHB + (g8 >> 1) * 16);
    // B: mat g -> row (g>>1)*8, col-bytes (g&1)*16
    const uint32_t b_lane_off =
        (uint32_t)(TILE_BYTES +
                   (wn * 64 + ((g8 >> 1) << 3) + l8) * PITCHB + (g8 & 1) * 16);

    // cp.async mapping: 8 chunks/thread/stage, 128B coalesced rows.
    const int ld_row = t >> 3;   // 0..31 (+32 per p&3)
    const int ld_part = t & 7;   // 16B offset in 128B row

    float acc[2][8][4];
#pragma unroll
    for (int mt = 0; mt < 2; mt++)
#pragma unroll
        for (int nt = 0; nt < 8; nt++)
#pragma unroll
            for (int i = 0; i < 4; i++) acc[mt][nt][i] = 0.f;

#define LOAD_STAGE(SB, K0)                                                     \
    do {                                                                       \
        _Pragma("unroll") for (int p = 0; p < 8; p++) {                        \
            const int mat = p >> 2;                                            \
            const int row = ((p & 3) << 5) + ld_row;                           \
            const __half* src = (mat == 0)                                     \
                ? g_ah + (size_t)(m0 + row) * GK + (K0) + ld_part * 8          \
                : Bt + (size_t)(n0 + row) * GK + (K0) + ld_part * 8;           \
            cp_async16((SB) + mat * TILE_BYTES + row * PITCHB + ld_part * 16,  \
                       src);                                                   \
        }                                                                      \
        asm volatile("cp.async.commit_group;" ::: "memory");                   \
    } while (0)

    LOAD_STAGE(sbase, 0);

    for (int it = 0; it < NKT; it++) {
        const uint32_t sstage = sbase + (it & 1) * STAGE_BYTES;
        const uint32_t snxt = sbase + ((it & 1) ^ 1) * STAGE_BYTES;
        if (it + 1 < NKT) {
            LOAD_STAGE(snxt, (it + 1) * BKK);
            asm volatile("cp.async.wait_group 1;" ::: "memory");
        } else {
            asm volatile("cp.async.wait_group 0;" ::: "memory");
        }
        __syncthreads();

        const uint32_t abase = sstage + a_lane_off;
        const uint32_t bbase = sstage + b_lane_off;

#pragma unroll
        for (int ks = 0; ks < 4; ks++) {  // 4 x k16 per 64-k tile
            uint32_t afr[2][4];
            ldmx4(afr[0], abase + ks * 32);
            ldmx4(afr[1], abase + 16 * PITCHB + ks * 32);
            uint32_t bfr[4][4];
#pragma unroll
            for (int p = 0; p < 4; p++)
                ldmx4(bfr[p], bbase + p * 16 * PITCHB + ks * 32);
#pragma unroll
            for (int mt = 0; mt < 2; mt++)
#pragma unroll
                for (int nt = 0; nt < 8; nt++) {
                    const int p = nt >> 1;
                    const int o = (nt & 1) * 2;
                    mma_f16(acc[mt][nt], afr[mt][0], afr[mt][1], afr[mt][2],
                            afr[mt][3], bfr[p][o], bfr[p][o + 1]);
                }
        }
        __syncthreads();
    }

    // Epilogue
#pragma unroll
    for (int mt = 0; mt < 2; mt++) {
#pragma unroll
        for (int nt = 0; nt < 8; nt++) {
            int r0 = m0 + wm * 32 + mt * 16 + qr;
            int c0 = n0 + wn * 64 + nt * 8 + 2 * qc;
            *(float2*)(dst + (size_t)r0 * GN + c0) =
                make_float2(acc[mt][nt][0], acc[mt][nt][1]);
            *(float2*)(dst + (size_t)(r0 + 8) * GN + c0) =
                make_float2(acc[mt][nt][2], acc[mt][nt][3]);
        }
    }
#undef LOAD_STAGE
}

// ---------------------------------------------------------------------------
// Attention: one block per (h, n, b). 16 queries x 20 keys x 128 dims.
// Score phase register-tiled 2x2 (halves smem traffic), dq skew vs conflicts.
// ---------------------------------------------------------------------------
#define SKP 132

__global__ __launch_bounds__(256)
void attn_kernel(const float* __restrict__ q, const float* __restrict__ k,
                 const float* __restrict__ v,
                 float* __restrict__ out) {
    __shared__ float sq[16][SKP];
    __shared__ float sk[20][SKP];
    __shared__ float sv[20][SKP];
    __shared__ float sattn[16][20];

    const int t = threadIdx.x;
    const int h = blockIdx.x;
    const int n = blockIdx.y;
    const int b = blockIdx.z;

    const size_t qkv_base = (((size_t)(b * (NN * BSQ) + n * BSQ)) * NHH + h) * DHH;
    const size_t chs_base = ((size_t)((b * NN + n) * LL)) * GN + h * DHH;

    for (int i = t; i < 16 * 32; i += 256) {
        int s = i >> 5, dq = i & 31;
        *(float4*)&sq[s][dq * 4] =
            *(const float4*)(q + qkv_base + (size_t)s * 2048 + dq * 4);
    }
    for (int i = t; i < 4 * 32; i += 256) {
        int j = i >> 5, dq = i & 31;
        *(float4*)&sk[j][dq * 4] =
            *(const float4*)(g_kchs + chs_base + (size_t)j * GN + dq * 4);
        *(float4*)&sv[j][dq * 4] =
            *(const float4*)(g_vchs + chs_base + (size_t)j * GN + dq * 4);
    }
    for (int i = t; i < 16 * 32; i += 256) {
        int s = i >> 5, dq = i & 31;
        *(float4*)&sk[4 + s][dq * 4] =
            *(const float4*)(k + qkv_base + (size_t)s * 2048 + dq * 4);
        *(float4*)&sv[4 + s][dq * 4] =
            *(const float4*)(v + qkv_base + (size_t)s * 2048 + dq * 4);
    }
    __syncthreads();

    // scores: 2x2 register tile per thread; 8 s-tiles x 10 j-tiles = 80 threads
    if (t < 80) {
        const int st = t / 10, jt = t % 10;
        const int s0 = st * 2, j0 = jt * 2;
        const float4* q0 = (const float4*)&sq[s0][0];
        const float4* q1 = (const float4*)&sq[s0 + 1][0];
        const float4* k0r = (const float4*)&sk[j0][0];
        const float4* k1r = (const float4*)&sk[j0 + 1][0];
        float a00 = 0.f, a01 = 0.f, a10 = 0.f, a11 = 0.f;
#pragma unroll 4
        for (int i = 0; i < 32; i++) {
            const int dq = (i + jt * 3) & 31;  // skew vs bank conflicts
            float4 qa = q0[dq], qb = q1[dq];
            float4 ka = k0r[dq], kb = k1r[dq];
            a00 += qa.x * ka.x + qa.y * ka.y + qa.z * ka.z + qa.w * ka.w;
            a01 += qa.x * kb.x + qa.y * kb.y + qa.z * kb.z + qa.w * kb.w;
            a10 += qb.x * ka.x + qb.y * ka.y + qb.z * ka.z + qb.w * ka.w;
            a11 += qb.x * kb.x + qb.y * kb.y + qb.z * kb.z + qb.w * kb.w;
        }
        sattn[s0][j0] = a00 * ATT_SCALE;
        sattn[s0][j0 + 1] = a01 * ATT_SCALE;
        sattn[s0 + 1][j0] = a10 * ATT_SCALE;
        sattn[s0 + 1][j0 + 1] = a11 * ATT_SCALE;
    }
    __syncthreads();

    if (t < 16) {
        float mx = -1e30f;
#pragma unroll
        for (int j = 0; j < 20; j++) mx = fmaxf(mx, sattn[t][j]);
        float sum = 0.f;
        float e[20];
#pragma unroll
        for (int j = 0; j < 20; j++) {
            e[j] = expf(sattn[t][j] - mx);
            sum += e[j];
        }
        float inv = 1.f / sum;
#pragma unroll
        for (int j = 0; j < 20; j++) sattn[t][j] = e[j] * inv;
    }
    __syncthreads();

    const int d = t & 127;
    const int shalf = t >> 7;
    float vreg[20];
#pragma unroll
    for (int j = 0; j < 20; j++) vreg[j] = sv[j][d];
    const float mval = g_maskf[b * NN + n];
    float* obase = out + ((size_t)(b * (NN * BSQ) + n * BSQ)) * GN + h * DHH + d;
    for (int s = shalf; s < 16; s += 2) {
        float acc = 0.f;
#pragma unroll
        for (int j = 0; j < 20; j++) acc += sattn[s][j] * vreg[j];
        obase[(size_t)s * GN] = acc * mval;
    }
}

// ---------------------------------------------------------------------------
extern "C" void kernel_launch(void* const* d_in, const int* in_sizes, int n_in,
                              void* d_out, int out_size) {
    const float* hs = (const float*)d_in[0];
    const unsigned char* anchors = (const unsigned char*)d_in[1];
    const unsigned char* maskb = (const unsigned char*)d_in[2];
    const float* q = (const float*)d_in[3];
    const float* k = (const float*)d_in[4];
    const float* v = (const float*)d_in[5];
    const float* Wk = (const float*)d_in[6];
    const float* Wv = (const float*)d_in[7];
    float* out = (float*)d_out;

    cudaFuncSetAttribute(gemm_f16_kernel,
                         cudaFuncAttributeMaxDynamicSharedMemorySize,
                         GEMM_DSMEM);

    decode_small_kernel<<<1, 256>>>(anchors, maskb);
    gather_f16_kernel<<<4096, 256>>>(hs);
    transpose_f16_kernel<<<dim3(64, 64, 2), 256>>>(Wk, Wv);

    gemm_f16_kernel<<<dim3(GN / BN, GM / BM, 2), 256, GEMM_DSMEM>>>();

    dim3 agrid(NHH, NN, BB);  // 16 x 256 x 2
    attn_kernel<<<agrid, 256>>>(q, k, v, out);
}